// round 14
// baseline (speedup 1.0000x reference)
#include <cuda_runtime.h>

#define TT 512
#define BTILE 16
#define NTHREADS 512

typedef unsigned long long ull;

struct Smem {
    float w0[64 * 256];    // [k][j*4+gate] <- w_hh0[(gate*64+j)*64+k]
    float wi1[64 * 256];   // same regroup of w_ih1
    float wh1[64 * 256];   // same regroup of w_hh1
    float hA[2][64 * 16];  // layer-0 hidden, [buf][k*16 + b]
    float hB[2][64 * 16];  // layer-1 hidden
    ull   P[8 * 256];      // Gab->Gc ih1 lower-half partial gates: [i][slot]
    float xs[2][BTILE * 4];
};

__device__ __forceinline__ ull pack2(float x, float y) {
    ull r;
    asm("mov.b64 %0, {%1, %2};" : "=l"(r) : "f"(x), "f"(y));
    return r;
}
__device__ __forceinline__ void unpack2(ull v, float& x, float& y) {
    asm("mov.b64 {%0, %1}, %2;" : "=f"(x), "=f"(y) : "l"(v));
}
__device__ __forceinline__ ull fma2(ull a, ull b, ull c) {
    ull d;
    asm("fma.rn.f32x2 %0, %1, %2, %3;" : "=l"(d) : "l"(a), "l"(b), "l"(c));
    return d;
}
__device__ __forceinline__ ull add2(ull a, ull b) {
    ull d;
    asm("add.rn.f32x2 %0, %1, %2;" : "=l"(d) : "l"(a), "l"(b));
    return d;
}
__device__ __forceinline__ float tanh_ap(float x) {
    float y;
    asm("tanh.approx.f32 %0, %1;" : "=f"(y) : "f"(x));
    return y;
}
__device__ __forceinline__ float sig_ap(float x) {
    return fmaf(tanh_ap(x * 0.5f), 0.5f, 0.5f);
}

// acc[g*2+p]: gate g, row-pair p -> 4 cells, c in regs
__device__ __forceinline__ void cell4(const ull acc[8], float c[4], float hn[4]) {
#pragma unroll
    for (int p = 0; p < 2; p++) {
        float i0, i1, f0, f1, g0, g1, o0, o1;
        unpack2(acc[0 * 2 + p], i0, i1);
        unpack2(acc[1 * 2 + p], f0, f1);
        unpack2(acc[2 * 2 + p], g0, g1);
        unpack2(acc[3 * 2 + p], o0, o1);
        float I0 = sig_ap(i0), F0 = sig_ap(f0), G0 = tanh_ap(g0), O0 = sig_ap(o0);
        c[2 * p] = F0 * c[2 * p] + I0 * G0;
        hn[2 * p] = O0 * tanh_ap(c[2 * p]);
        float I1 = sig_ap(i1), F1 = sig_ap(f1), G1 = tanh_ap(g1), O1 = sig_ap(o1);
        c[2 * p + 1] = F1 * c[2 * p + 1] + I1 * G1;
        hn[2 * p + 1] = O1 * tanh_ap(c[2 * p + 1]);
    }
}

// 8 fma2 for one k: gates of 4 batch rows against one float4 of weights
__device__ __forceinline__ void mv8(ull acc[8], ulonglong2 hp, float4 wv) {
    acc[0] = fma2(hp.x, pack2(wv.x, wv.x), acc[0]);
    acc[1] = fma2(hp.y, pack2(wv.x, wv.x), acc[1]);
    acc[2] = fma2(hp.x, pack2(wv.y, wv.y), acc[2]);
    acc[3] = fma2(hp.y, pack2(wv.y, wv.y), acc[3]);
    acc[4] = fma2(hp.x, pack2(wv.z, wv.z), acc[4]);
    acc[5] = fma2(hp.y, pack2(wv.z, wv.z), acc[5]);
    acc[6] = fma2(hp.x, pack2(wv.w, wv.w), acc[6]);
    acc[7] = fma2(hp.y, pack2(wv.w, wv.w), acc[7]);
}

__global__ void __launch_bounds__(NTHREADS, 1)
lstm_fused_kernel(const float* __restrict__ x,
                  const float* __restrict__ w_ih0, const float* __restrict__ w_hh0,
                  const float* __restrict__ b_ih0, const float* __restrict__ b_hh0,
                  const float* __restrict__ w_ih1, const float* __restrict__ w_hh1,
                  const float* __restrict__ b_ih1, const float* __restrict__ b_hh1,
                  const float* __restrict__ fc_w, const float* __restrict__ fc_b,
                  float* __restrict__ out)
{
    extern __shared__ __align__(16) unsigned char smem_raw[];
    Smem& sh = *reinterpret_cast<Smem*>(smem_raw);
    const int tid = threadIdx.x;
    const int b0 = blockIdx.x * BTILE;

    // ---- stage recurrent weights, regrouped: [k][j*4+gate] ----
    for (int e = tid; e < 64 * 256; e += NTHREADS) {
        int row = e >> 6, k = e & 63;
        int gate = row >> 6, jj = row & 63;
        int d = k * 256 + jj * 4 + gate;
        sh.w0[d] = w_hh0[e];
        sh.wi1[d] = w_ih1[e];
        sh.wh1[d] = w_hh1[e];
    }
    // ---- zero h buffers ----
    for (int e = tid; e < 1024; e += NTHREADS) {
        sh.hA[0][e] = 0.f; sh.hA[1][e] = 0.f;
        sh.hB[0][e] = 0.f; sh.hB[1][e] = 0.f;
    }
    // ---- preload x for t=0 (Gc warp 8, lanes 0-15) ----
    if (tid >= 256 && tid < 256 + BTILE) {
        int b = tid - 256;
        *(float4*)&sh.xs[0][b * 4] = ((const float4*)x)[(size_t)(b0 + b) * TT];
    }

    const int wid = tid >> 5;
    const int lane = tid & 31;
    const bool isGab = (wid < 8);          // Gab: layer-0 + ih1[k<32]; Gc: hh1 + ih1[k>=32] + cell
    const int lw = wid & 7;
    const int j = lw * 8 + (lane >> 2);    // hidden unit 0..63
    const int quad = lane & 3;
    const int q4 = quad * 4;               // rows q4..q4+3
    const int slot = lw * 32 + lane;       // P slot (same for Gab/Gc pair)

    float wi0[16], bias0[4];
    ull bias1[4] = {0, 0, 0, 0};
    if (isGab) {
#pragma unroll
        for (int g = 0; g < 4; g++) {
            float4 wv = *(const float4*)(w_ih0 + (g * 64 + j) * 4);
            wi0[g * 4 + 0] = wv.x; wi0[g * 4 + 1] = wv.y;
            wi0[g * 4 + 2] = wv.z; wi0[g * 4 + 3] = wv.w;
            bias0[g] = b_ih0[g * 64 + j] + b_hh0[g * 64 + j];
            float bb = b_ih1[g * 64 + j] + b_hh1[g * 64 + j];
            bias1[g] = pack2(bb, bb);
        }
    }
    float c[4];
#pragma unroll
    for (int i = 0; i < 4; i++) c[i] = 0.f;

    __syncthreads();

    // ============ pipelined recurrence ============
    // round r: Gab: layer-0 t=r + ih1[k<32] for t=r-1 (shares ONE hA load on k<32);
    //          Gc:  hh1 full + ih1[k>=32] (own hA read) + combine + cell for t=r-1
    for (int r = 0; r <= TT; r++) {
        float4 xpre;
        const bool pre = (tid >= 256) && (tid < 256 + BTILE) && (r <= TT - 2);
        if (pre) xpre = ((const float4*)x)[(size_t)(b0 + (tid - 256)) * TT + (r + 1)];

        if (isGab) {
            ull a0[8], a1[8];
            // layer-0 x projection for rows q4..q4+3
            const float4* xp = (const float4*)sh.xs[r & 1];
#pragma unroll
            for (int p = 0; p < 2; p++) {
                float4 xa = xp[q4 + 2 * p];
                float4 xb = xp[q4 + 2 * p + 1];
#pragma unroll
                for (int g = 0; g < 4; g++) {
                    float s0 = bias0[g] + wi0[g*4]*xa.x + wi0[g*4+1]*xa.y
                                        + wi0[g*4+2]*xa.z + wi0[g*4+3]*xa.w;
                    float s1 = bias0[g] + wi0[g*4]*xb.x + wi0[g*4+1]*xb.y
                                        + wi0[g*4+2]*xb.z + wi0[g*4+3]*xb.w;
                    a0[g * 2 + p] = pack2(s0, s1);
                }
            }
#pragma unroll
            for (int g = 0; g < 4; g++) {
                a1[g * 2] = bias1[g];
                a1[g * 2 + 1] = bias1[g];
            }
            const float* hr = sh.hA[r & 1] + q4;
            const float* wp0 = sh.w0 + j * 4;
            const float* wp1 = sh.wi1 + j * 4;
            // k < 32: one h load feeds both matvecs
#pragma unroll 8
            for (int k = 0; k < 32; k++) {
                ulonglong2 hp = *(const ulonglong2*)(hr + k * 16);
                float4 w = *(const float4*)(wp0 + (k << 8));
                mv8(a0, hp, w);
                float4 v = *(const float4*)(wp1 + (k << 8));
                mv8(a1, hp, v);
            }
            // k >= 32: layer-0 only
#pragma unroll 8
            for (int k = 32; k < 64; k++) {
                ulonglong2 hp = *(const ulonglong2*)(hr + k * 16);
                float4 w = *(const float4*)(wp0 + (k << 8));
                mv8(a0, hp, w);
            }
            if (r >= 1) {
#pragma unroll
                for (int i = 0; i < 8; i++) sh.P[i * 256 + slot] = a1[i];
                asm volatile("bar.sync %0, 64;" :: "r"(1 + lw) : "memory");
            }
            if (r < TT) {
                float hn[4];
                cell4(a0, c, hn);
                *(float4*)(sh.hA[(r + 1) & 1] + j * 16 + q4) =
                    make_float4(hn[0], hn[1], hn[2], hn[3]);
            }
        } else {
            if (r >= 1) {
                ull acc[8], a1[8];
#pragma unroll
                for (int i = 0; i < 8; i++) { acc[i] = 0ull; a1[i] = 0ull; }
                const float* hb = sh.hB[r & 1] + q4;
                const float* ha = sh.hA[r & 1] + q4;
                const float* wph = sh.wh1 + j * 4;
                const float* wpi = sh.wi1 + j * 4;
                // hh1 over full k
#pragma unroll 8
                for (int k = 0; k < 64; k++) {
                    ulonglong2 hp = *(const ulonglong2*)(hb + k * 16);
                    float4 w = *(const float4*)(wph + (k << 8));
                    mv8(acc, hp, w);
                }
                // ih1 upper half (k >= 32), reading hA directly
#pragma unroll 8
                for (int k = 32; k < 64; k++) {
                    ulonglong2 hp = *(const ulonglong2*)(ha + k * 16);
                    float4 v = *(const float4*)(wpi + (k << 8));
                    mv8(a1, hp, v);
                }
                asm volatile("bar.sync %0, 64;" :: "r"(1 + lw) : "memory");
#pragma unroll
                for (int i = 0; i < 8; i++)
                    acc[i] = add2(acc[i], add2(a1[i], sh.P[i * 256 + slot]));
                float hn[4];
                cell4(acc, c, hn);
                *(float4*)(sh.hB[(r + 1) & 1] + j * 16 + q4) =
                    make_float4(hn[0], hn[1], hn[2], hn[3]);
            }
        }

        if (pre) *(float4*)&sh.xs[(r + 1) & 1][(tid - 256) * 4] = xpre;
        __syncthreads();
    }

    // ============ FC + tanh epilogue ============
    // h_n (layer 1, t=511) finalized at r=512 -> hB[1].
    for (int e = tid; e < 4096; e += NTHREADS) {
        int jj = e >> 6, k = e & 63;
        sh.w0[k * 64 + jj] = fc_w[e]; // transpose: [k][j]
    }
    __syncthreads();

    if (tid < 256) {
        const int q = tid >> 6;  // 4 batch rows each
        const int jo = tid & 63;
        const float* hfin = sh.hB[1];
        float fb = fc_b[jo];
        float acc[4];
#pragma unroll
        for (int m = 0; m < 4; m++) acc[m] = fb;
#pragma unroll 8
        for (int k = 0; k < 64; k++) {
            float w = sh.w0[k * 64 + jo];
#pragma unroll
            for (int m = 0; m < 4; m++)
                acc[m] += w * hfin[k * 16 + q * 4 + m];
        }
#pragma unroll
        for (int m = 0; m < 4; m++)
            out[(size_t)(b0 + q * 4 + m) * 64 + jo] = tanh_ap(acc[m]);
    }
}

extern "C" void kernel_launch(void* const* d_in, const int* in_sizes, int n_in,
                              void* d_out, int out_size) {
    const float* x     = (const float*)d_in[0];
    const float* w_ih0 = (const float*)d_in[1];
    const float* w_hh0 = (const float*)d_in[2];
    const float* b_ih0 = (const float*)d_in[3];
    const float* b_hh0 = (const float*)d_in[4];
    const float* w_ih1 = (const float*)d_in[5];
    const float* w_hh1 = (const float*)d_in[6];
    const float* b_ih1 = (const float*)d_in[7];
    const float* b_hh1 = (const float*)d_in[8];
    const float* fc_w  = (const float*)d_in[9];
    const float* fc_b  = (const float*)d_in[10];
    float* out = (float*)d_out;

    const int smem = (int)sizeof(Smem);
    cudaFuncSetAttribute(lstm_fused_kernel,
                         cudaFuncAttributeMaxDynamicSharedMemorySize, smem);
    lstm_fused_kernel<<<2048 / BTILE, NTHREADS, smem>>>(
        x, w_ih0, w_hh0, b_ih0, b_hh0,
        w_ih1, w_hh1, b_ih1, b_hh1, fc_w, fc_b, out);
}

// round 15
// speedup vs baseline: 1.0566x; 1.0566x over previous
#include <cuda_runtime.h>

#define TT 512
#define BTILE 16
#define NTHREADS 512

typedef unsigned long long ull;

struct Smem {
    float w0[64 * 256];    // [k][j*4+gate] <- w_hh0[(gate*64+j)*64+k]
    float wi1[64 * 256];   // same regroup of w_ih1
    float wh1[64 * 256];   // same regroup of w_hh1
    float hA[2][64 * 16];  // layer-0 hidden, [buf][k*16 + b]
    float hB[2][64 * 16];  // layer-1 hidden
    ull   P[8 * 256];      // Gab->Gc ih1 partial gates: [i][slot]
    float xs[2][BTILE * 4];
};

__device__ __forceinline__ ull pack2(float x, float y) {
    ull r;
    asm("mov.b64 %0, {%1, %2};" : "=l"(r) : "f"(x), "f"(y));
    return r;
}
__device__ __forceinline__ void unpack2(ull v, float& x, float& y) {
    asm("mov.b64 {%0, %1}, %2;" : "=f"(x), "=f"(y) : "l"(v));
}
__device__ __forceinline__ ull fma2(ull a, ull b, ull c) {
    ull d;
    asm("fma.rn.f32x2 %0, %1, %2, %3;" : "=l"(d) : "l"(a), "l"(b), "l"(c));
    return d;
}
__device__ __forceinline__ ull add2(ull a, ull b) {
    ull d;
    asm("add.rn.f32x2 %0, %1, %2;" : "=l"(d) : "l"(a), "l"(b));
    return d;
}
__device__ __forceinline__ float tanh_ap(float x) {
    float y;
    asm("tanh.approx.f32 %0, %1;" : "=f"(y) : "f"(x));
    return y;
}
__device__ __forceinline__ float sig_ap(float x) {
    return fmaf(tanh_ap(x * 0.5f), 0.5f, 0.5f);
}

// one cell from gate-pair accumulators (I,F) and (G,O); returns new h
__device__ __forceinline__ float cellh(ull aIF, ull aGO, float& c) {
    float gi, gf, gg, go;
    unpack2(aIF, gi, gf);
    unpack2(aGO, gg, go);
    float I = sig_ap(gi), F = sig_ap(gf), G = tanh_ap(gg), O = sig_ap(go);
    c = F * c + I * G;
    return O * tanh_ap(c);
}

__global__ void __launch_bounds__(NTHREADS, 1)
lstm_fused_kernel(const float* __restrict__ x,
                  const float* __restrict__ w_ih0, const float* __restrict__ w_hh0,
                  const float* __restrict__ b_ih0, const float* __restrict__ b_hh0,
                  const float* __restrict__ w_ih1, const float* __restrict__ w_hh1,
                  const float* __restrict__ b_ih1, const float* __restrict__ b_hh1,
                  const float* __restrict__ fc_w, const float* __restrict__ fc_b,
                  float* __restrict__ out)
{
    extern __shared__ __align__(16) unsigned char smem_raw[];
    Smem& sh = *reinterpret_cast<Smem*>(smem_raw);
    const int tid = threadIdx.x;
    const int b0 = blockIdx.x * BTILE;

    // ---- stage recurrent weights, regrouped: [k][j*4+gate] ----
    for (int e = tid; e < 64 * 256; e += NTHREADS) {
        int row = e >> 6, k = e & 63;
        int gate = row >> 6, jj = row & 63;
        int d = k * 256 + jj * 4 + gate;
        sh.w0[d] = w_hh0[e];
        sh.wi1[d] = w_ih1[e];
        sh.wh1[d] = w_hh1[e];
    }
    // ---- zero h buffers ----
    for (int e = tid; e < 1024; e += NTHREADS) {
        sh.hA[0][e] = 0.f; sh.hA[1][e] = 0.f;
        sh.hB[0][e] = 0.f; sh.hB[1][e] = 0.f;
    }
    // ---- preload x for t=0 (Gc warp 8, lanes 0-15) ----
    if (tid >= 256 && tid < 256 + BTILE) {
        int b = tid - 256;
        *(float4*)&sh.xs[0][b * 4] = ((const float4*)x)[(size_t)(b0 + b) * TT];
    }

    const int wid = tid >> 5;
    const int lane = tid & 31;
    const bool isGab = (wid < 8);          // Gab: layer-0 + ih1 (shared h load); Gc: hh1 + cell
    const int lw = wid & 7;
    const int j = lw * 8 + (lane >> 2);    // hidden unit 0..63
    const int quad = lane & 3;
    const int q4 = quad * 4;               // rows q4..q4+3
    const int slot = lw * 32 + lane;       // P slot (same for Gab/Gc pair)

    float wi0[16], bias0[4];
    ull biasIF = 0, biasGO = 0;
    if (isGab) {
#pragma unroll
        for (int g = 0; g < 4; g++) {
            float4 wv = *(const float4*)(w_ih0 + (g * 64 + j) * 4);
            wi0[g * 4 + 0] = wv.x; wi0[g * 4 + 1] = wv.y;
            wi0[g * 4 + 2] = wv.z; wi0[g * 4 + 3] = wv.w;
            bias0[g] = b_ih0[g * 64 + j] + b_hh0[g * 64 + j];
        }
        float bi = b_ih1[0 * 64 + j] + b_hh1[0 * 64 + j];
        float bf = b_ih1[1 * 64 + j] + b_hh1[1 * 64 + j];
        float bg = b_ih1[2 * 64 + j] + b_hh1[2 * 64 + j];
        float bo = b_ih1[3 * 64 + j] + b_hh1[3 * 64 + j];
        biasIF = pack2(bi, bf);
        biasGO = pack2(bg, bo);
    }
    float c[4];
#pragma unroll
    for (int i = 0; i < 4; i++) c[i] = 0.f;

    __syncthreads();

    // ============ pipelined recurrence ============
    // round r: Gab: layer-0 t=r + ih1 partial for t=r-1 (ONE hA load feeds both);
    //          Gc:  hh1 matvec for t=r-1 + combine + cell
    for (int r = 0; r <= TT; r++) {
        float4 xpre;
        const bool pre = (tid >= 256) && (tid < 256 + BTILE) && (r <= TT - 2);
        if (pre) xpre = ((const float4*)x)[(size_t)(b0 + (tid - 256)) * TT + (r + 1)];

        if (isGab) {
            // gate-pair accumulators: aIF0/aGO0 = layer-0, aIF1/aGO1 = ih1
            ull aIF0[4], aGO0[4], aIF1[4], aGO1[4];
            const float4* xp = (const float4*)sh.xs[r & 1];
#pragma unroll
            for (int b = 0; b < 4; b++) {
                float4 xv = xp[q4 + b];
                float si = bias0[0] + wi0[0]*xv.x + wi0[1]*xv.y + wi0[2]*xv.z + wi0[3]*xv.w;
                float sf = bias0[1] + wi0[4]*xv.x + wi0[5]*xv.y + wi0[6]*xv.z + wi0[7]*xv.w;
                float sg = bias0[2] + wi0[8]*xv.x + wi0[9]*xv.y + wi0[10]*xv.z + wi0[11]*xv.w;
                float so = bias0[3] + wi0[12]*xv.x + wi0[13]*xv.y + wi0[14]*xv.z + wi0[15]*xv.w;
                aIF0[b] = pack2(si, sf);
                aGO0[b] = pack2(sg, so);
                aIF1[b] = biasIF;
                aGO1[b] = biasGO;
            }
            const float* hr = sh.hA[r & 1] + q4;
            const float* wp0 = sh.w0 + j * 4;
            const float* wp1 = sh.wi1 + j * 4;
            // per k: 3 LDS.128 + 4 h-packs + 16 fma2 (weights consumed directly)
#pragma unroll 8
            for (int k = 0; k < 64; k++) {
                float4 hv = *(const float4*)(hr + k * 16);   // rows q4..q4+3
                ull hd0 = pack2(hv.x, hv.x);
                ull hd1 = pack2(hv.y, hv.y);
                ull hd2 = pack2(hv.z, hv.z);
                ull hd3 = pack2(hv.w, hv.w);
                ulonglong2 w01 = *(const ulonglong2*)(wp0 + (k << 8)); // (wI,wF),(wG,wO)
                aIF0[0] = fma2(hd0, w01.x, aIF0[0]); aGO0[0] = fma2(hd0, w01.y, aGO0[0]);
                aIF0[1] = fma2(hd1, w01.x, aIF0[1]); aGO0[1] = fma2(hd1, w01.y, aGO0[1]);
                aIF0[2] = fma2(hd2, w01.x, aIF0[2]); aGO0[2] = fma2(hd2, w01.y, aGO0[2]);
                aIF0[3] = fma2(hd3, w01.x, aIF0[3]); aGO0[3] = fma2(hd3, w01.y, aGO0[3]);
                ulonglong2 v01 = *(const ulonglong2*)(wp1 + (k << 8));
                aIF1[0] = fma2(hd0, v01.x, aIF1[0]); aGO1[0] = fma2(hd0, v01.y, aGO1[0]);
                aIF1[1] = fma2(hd1, v01.x, aIF1[1]); aGO1[1] = fma2(hd1, v01.y, aGO1[1]);
                aIF1[2] = fma2(hd2, v01.x, aIF1[2]); aGO1[2] = fma2(hd2, v01.y, aGO1[2]);
                aIF1[3] = fma2(hd3, v01.x, aIF1[3]); aGO1[3] = fma2(hd3, v01.y, aGO1[3]);
            }
            if (r >= 1) {
#pragma unroll
                for (int b = 0; b < 4; b++) {
                    sh.P[b * 256 + slot] = aIF1[b];
                    sh.P[(4 + b) * 256 + slot] = aGO1[b];
                }
                asm volatile("bar.sync %0, 64;" :: "r"(1 + lw) : "memory");
            }
            if (r < TT) {
                float4 hn;
                hn.x = cellh(aIF0[0], aGO0[0], c[0]);
                hn.y = cellh(aIF0[1], aGO0[1], c[1]);
                hn.z = cellh(aIF0[2], aGO0[2], c[2]);
                hn.w = cellh(aIF0[3], aGO0[3], c[3]);
                *(float4*)(sh.hA[(r + 1) & 1] + j * 16 + q4) = hn;
            }
        } else {
            if (r >= 1) {
                ull bIF[4], bGO[4];
#pragma unroll
                for (int b = 0; b < 4; b++) { bIF[b] = 0ull; bGO[b] = 0ull; }
                const float* hb = sh.hB[r & 1] + q4;
                const float* wph = sh.wh1 + j * 4;
                // per k: 2 LDS.128 + 4 h-packs + 8 fma2
#pragma unroll 8
                for (int k = 0; k < 64; k++) {
                    float4 hv = *(const float4*)(hb + k * 16);
                    ull hd0 = pack2(hv.x, hv.x);
                    ull hd1 = pack2(hv.y, hv.y);
                    ull hd2 = pack2(hv.z, hv.z);
                    ull hd3 = pack2(hv.w, hv.w);
                    ulonglong2 w01 = *(const ulonglong2*)(wph + (k << 8));
                    bIF[0] = fma2(hd0, w01.x, bIF[0]); bGO[0] = fma2(hd0, w01.y, bGO[0]);
                    bIF[1] = fma2(hd1, w01.x, bIF[1]); bGO[1] = fma2(hd1, w01.y, bGO[1]);
                    bIF[2] = fma2(hd2, w01.x, bIF[2]); bGO[2] = fma2(hd2, w01.y, bGO[2]);
                    bIF[3] = fma2(hd3, w01.x, bIF[3]); bGO[3] = fma2(hd3, w01.y, bGO[3]);
                }
                asm volatile("bar.sync %0, 64;" :: "r"(1 + lw) : "memory");
                float4 hn;
                float hv0 = cellh(add2(bIF[0], sh.P[0 * 256 + slot]),
                                  add2(bGO[0], sh.P[4 * 256 + slot]), c[0]);
                float hv1 = cellh(add2(bIF[1], sh.P[1 * 256 + slot]),
                                  add2(bGO[1], sh.P[5 * 256 + slot]), c[1]);
                float hv2 = cellh(add2(bIF[2], sh.P[2 * 256 + slot]),
                                  add2(bGO[2], sh.P[6 * 256 + slot]), c[2]);
                float hv3 = cellh(add2(bIF[3], sh.P[3 * 256 + slot]),
                                  add2(bGO[3], sh.P[7 * 256 + slot]), c[3]);
                hn.x = hv0; hn.y = hv1; hn.z = hv2; hn.w = hv3;
                *(float4*)(sh.hB[(r + 1) & 1] + j * 16 + q4) = hn;
            }
        }

        if (pre) *(float4*)&sh.xs[(r + 1) & 1][(tid - 256) * 4] = xpre;
        __syncthreads();
    }

    // ============ FC + tanh epilogue ============
    // h_n (layer 1, t=511) finalized at r=512 -> hB[1].
    for (int e = tid; e < 4096; e += NTHREADS) {
        int jj = e >> 6, k = e & 63;
        sh.w0[k * 64 + jj] = fc_w[e]; // transpose: [k][j]
    }
    __syncthreads();

    if (tid < 256) {
        const int q = tid >> 6;  // 4 batch rows each
        const int jo = tid & 63;
        const float* hfin = sh.hB[1];
        float fb = fc_b[jo];
        float acc[4];
#pragma unroll
        for (int m = 0; m < 4; m++) acc[m] = fb;
#pragma unroll 8
        for (int k = 0; k < 64; k++) {
            float w = sh.w0[k * 64 + jo];
#pragma unroll
            for (int m = 0; m < 4; m++)
                acc[m] += w * hfin[k * 16 + q * 4 + m];
        }
#pragma unroll
        for (int m = 0; m < 4; m++)
            out[(size_t)(b0 + q * 4 + m) * 64 + jo] = tanh_ap(acc[m]);
    }
}

extern "C" void kernel_launch(void* const* d_in, const int* in_sizes, int n_in,
                              void* d_out, int out_size) {
    const float* x     = (const float*)d_in[0];
    const float* w_ih0 = (const float*)d_in[1];
    const float* w_hh0 = (const float*)d_in[2];
    const float* b_ih0 = (const float*)d_in[3];
    const float* b_hh0 = (const float*)d_in[4];
    const float* w_ih1 = (const float*)d_in[5];
    const float* w_hh1 = (const float*)d_in[6];
    const float* b_ih1 = (const float*)d_in[7];
    const float* b_hh1 = (const float*)d_in[8];
    const float* fc_w  = (const float*)d_in[9];
    const float* fc_b  = (const float*)d_in[10];
    float* out = (float*)d_out;

    const int smem = (int)sizeof(Smem);
    cudaFuncSetAttribute(lstm_fused_kernel,
                         cudaFuncAttributeMaxDynamicSharedMemorySize, smem);
    lstm_fused_kernel<<<2048 / BTILE, NTHREADS, smem>>>(
        x, w_ih0, w_hh0, b_ih0, b_hh0,
        w_ih1, w_hh1, b_ih1, b_hh1, fc_w, fc_b, out);
}